// round 1
// baseline (speedup 1.0000x reference)
#include <cuda_runtime.h>
#include <cstdint>

// Perception3D: 7-point stencil, 5 output groups per input channel.
// in : [B=4, C=16, D=64, H=64, W=64] fp32
// out: [B=4, C*G=80, D=64, H=64, W=64] fp32, out[b, c*5+g, ...]
//   g=0 ident, g=1 6-neighbor sum, g=2 gx (xp-xm), g=3 gy, g=4 gz
// Zero-padded shifts: xp[d]=s[d+1], xm[d]=s[d-1], etc.

#define Dz 64
#define Hy 64
#define Wx 64
#define PLANE (Dz * Hy * Wx)      // 262144 elems per (b,c) volume
#define W4 (Wx / 4)               // 16 float4 per row
#define BC 64                     // B*C
#define G 5

__global__ void __launch_bounds__(256, 8)
perception3d_kernel(const float* __restrict__ in, float* __restrict__ out) {
    // One thread handles one float4 (4 consecutive w).
    // Linear tid over BC * D * H * W4 = 64*64*64*16 = 4,194,304
    unsigned tid = blockIdx.x * blockDim.x + threadIdx.x;

    unsigned w4 = tid & (W4 - 1);          // 0..15
    unsigned h  = (tid >> 4) & (Hy - 1);   // 0..63
    unsigned d  = (tid >> 10) & (Dz - 1);  // 0..63
    unsigned bc = tid >> 16;               // 0..63

    const float* base = in + (size_t)bc * PLANE + (size_t)d * (Hy * Wx) + (size_t)h * Wx + (size_t)w4 * 4;

    // Center
    float4 c = *reinterpret_cast<const float4*>(base);

    // ±x (depth, stride H*W)
    float4 xp = (d + 1 < Dz) ? *reinterpret_cast<const float4*>(base + Hy * Wx)
                             : make_float4(0.f, 0.f, 0.f, 0.f);
    float4 xm = (d >= 1)     ? *reinterpret_cast<const float4*>(base - Hy * Wx)
                             : make_float4(0.f, 0.f, 0.f, 0.f);
    // ±y (height, stride W)
    float4 yp = (h + 1 < Hy) ? *reinterpret_cast<const float4*>(base + Wx)
                             : make_float4(0.f, 0.f, 0.f, 0.f);
    float4 ym = (h >= 1)     ? *reinterpret_cast<const float4*>(base - Wx)
                             : make_float4(0.f, 0.f, 0.f, 0.f);

    // ±z (within W): edge scalars
    float nextv = (w4 + 1 < W4) ? base[4]  : 0.f;
    float prevv = (w4 >= 1)     ? base[-1] : 0.f;

    float4 zp = make_float4(c.y, c.z, c.w, nextv);   // s[w+1]
    float4 zm = make_float4(prevv, c.x, c.y, c.z);   // s[w-1]

    // Compute groups
    float4 nsum, gx, gy, gz;
    nsum.x = xp.x + xm.x + yp.x + ym.x + zp.x + zm.x;
    nsum.y = xp.y + xm.y + yp.y + ym.y + zp.y + zm.y;
    nsum.z = xp.z + xm.z + yp.z + ym.z + zp.z + zm.z;
    nsum.w = xp.w + xm.w + yp.w + ym.w + zp.w + zm.w;
    gx.x = xp.x - xm.x; gx.y = xp.y - xm.y; gx.z = xp.z - xm.z; gx.w = xp.w - xm.w;
    gy.x = yp.x - ym.x; gy.y = yp.y - ym.y; gy.z = yp.z - ym.z; gy.w = yp.w - ym.w;
    gz.x = zp.x - zm.x; gz.y = zp.y - zm.y; gz.z = zp.z - zm.z; gz.w = zp.w - zm.w;

    // Output: b = bc/16, cch = bc%16; out channel = cch*5 + g
    unsigned b  = bc >> 4;
    unsigned cc = bc & 15;
    size_t spatial = (size_t)d * (Hy * Wx) + (size_t)h * Wx + (size_t)w4 * 4;
    float* obase = out + (size_t)b * (16 * G * PLANE) + (size_t)(cc * G) * PLANE + spatial;

    // Streaming stores (.cs) — output is never re-read; don't pollute L2.
    float4* o0 = reinterpret_cast<float4*>(obase);
    float4* o1 = reinterpret_cast<float4*>(obase + 1 * PLANE);
    float4* o2 = reinterpret_cast<float4*>(obase + 2 * PLANE);
    float4* o3 = reinterpret_cast<float4*>(obase + 3 * PLANE);
    float4* o4 = reinterpret_cast<float4*>(obase + 4 * PLANE);
    __stcs(o0, c);
    __stcs(o1, nsum);
    __stcs(o2, gx);
    __stcs(o3, gy);
    __stcs(o4, gz);
}

extern "C" void kernel_launch(void* const* d_in, const int* in_sizes, int n_in,
                              void* d_out, int out_size) {
    const float* in = (const float*)d_in[0];
    float* out = (float*)d_out;
    // Total threads: 64 * 64 * 64 * 16 = 4,194,304; 256 per block -> 16384 blocks
    perception3d_kernel<<<16384, 256>>>(in, out);
}